// round 1
// baseline (speedup 1.0000x reference)
#include <cuda_runtime.h>

#define NANCH 8400
#define BATCH 32
#define NCLS  80
#define BINS  16

// scratch accumulators: [0]=cls_sum [1]=iou_sum [2]=dfl_sum [3]=pos_count
__device__ double g_acc[4];

__global__ void zero_acc_kernel() {
    g_acc[0] = 0.0; g_acc[1] = 0.0; g_acc[2] = 0.0; g_acc[3] = 0.0;
}

__global__ void __launch_bounds__(256) yolo_loss_kernel(
    const float* __restrict__ p0, const float* __restrict__ p1, const float* __restrict__ p2,
    const float* __restrict__ gtb, const int* __restrict__ gtl, const int* __restrict__ mind)
{
    int g = blockIdx.x * blockDim.x + threadIdx.x;
    float cls_s = 0.f, iou_s = 0.f, dfl_s = 0.f;
    int cnt = 0;

    if (g < BATCH * NANCH) {
        int b = g / NANCH;
        int a = g - b * NANCH;

        const float* p; int HW, hw, W; float stride;
        if (a < 6400)      { p = p0; HW = 6400; hw = a;        W = 80; stride = 8.f;  }
        else if (a < 8000) { p = p1; HW = 1600; hw = a - 6400; W = 40; stride = 16.f; }
        else               { p = p2; HW = 400;  hw = a - 8000; W = 20; stride = 32.f; }

        const float* base = p + (size_t)b * 144 * HW + hw;

        int  ind = mind[g];
        bool pos = (ind >= 0);
        int  idx = pos ? ind : 0;
        int  lbl = gtl[b * 32 + idx];

        // ---------- classification focal loss: all 80 channels, every anchor ----------
        #pragma unroll 8
        for (int c = 0; c < NCLS; ++c) {
            float s  = base[(size_t)(64 + c) * HW];
            bool  t  = pos && (c == lbl);
            // softplus(s) = max(s,0) + log1p(exp(-|s|))
            float sp   = fmaxf(s, 0.f) + log1pf(__expf(-fabsf(s)));
            float ce   = t ? (sp - s) : sp;                 // ce = max(s,0) - s*t + log1p(exp(-|s|))
            float prob = __fdividef(1.f, 1.f + __expf(-s)); // sigmoid
            float omp  = t ? (1.f - prob) : prob;           // (1 - p_t)
            float at   = t ? 0.25f : 0.75f;                 // alpha_t
            cls_s += at * omp * omp * ce;
        }

        // ---------- DFL + IoU: only for positive anchors (skip 64 channels otherwise) ----------
        if (pos) {
            const float* tb4 = gtb + (size_t)(b * 32 + idx) * 4;
            float tx1 = tb4[0], ty1 = tb4[1], tx2 = tb4[2], ty2 = tb4[3];

            int wx = hw % W, wy = hw / W;
            float gx = (wx + 0.5f) * stride;
            float gy = (wy + 0.5f) * stride;

            float tgt0 = fmaxf(gx - tx1, 0.f);
            float tgt1 = fmaxf(gy - ty1, 0.f);
            float tgt2 = fmaxf(tx2 - gx, 0.f);
            float tgt3 = fmaxf(ty2 - gy, 0.f);
            float tgt[4] = { tgt0, tgt1, tgt2, tgt3 };

            float inv_stride = __fdividef(1.f, stride);
            float d[4];

            #pragma unroll
            for (int k = 0; k < 4; ++k) {
                float v[BINS];
                float m = -1e30f;
                #pragma unroll
                for (int j = 0; j < BINS; ++j) {
                    v[j] = base[(size_t)(k * BINS + j) * HW];
                    m = fmaxf(m, v[j]);
                }
                float S = 0.f, E = 0.f;
                #pragma unroll
                for (int j = 0; j < BINS; ++j) {
                    float e = __expf(v[j] - m);
                    S += e;
                    E += e * (float)j;
                }
                d[k] = __fdividef(E, S) * stride;

                float tb = fminf(tgt[k] * inv_stride, 15.f - 1e-6f); // tgt >= 0 already
                int   lo = (int)tb;                                  // floor, tb >= 0
                int   hi = min(lo + 1, BINS - 1);
                float aa = tb - (float)lo;
                float lS = logf(S);
                float lp_lo = v[lo] - m - lS;
                float lp_hi = v[hi] - m - lS;
                dfl_s -= (1.f - aa) * lp_lo + aa * lp_hi;
            }

            float px1 = gx - d[0], py1 = gy - d[1];
            float px2 = gx + d[2], py2 = gy + d[3];
            float ix1 = fmaxf(px1, tx1), iy1 = fmaxf(py1, ty1);
            float ix2 = fminf(px2, tx2), iy2 = fminf(py2, ty2);
            float inter  = fmaxf(ix2 - ix1, 0.f) * fmaxf(iy2 - iy1, 0.f);
            float area_p = fmaxf(px2 - px1, 0.f) * fmaxf(py2 - py1, 0.f);
            float area_t = fmaxf(tx2 - tx1, 0.f) * fmaxf(ty2 - ty1, 0.f);
            float iou = inter / (area_p + area_t - inter + 1e-7f);
            iou_s += 1.f - iou;
            cnt++;
        }
    }

    // ---------- reduction: warp shuffle -> shared -> one double atomic set per block ----------
    #pragma unroll
    for (int o = 16; o > 0; o >>= 1) {
        cls_s += __shfl_down_sync(0xffffffffu, cls_s, o);
        iou_s += __shfl_down_sync(0xffffffffu, iou_s, o);
        dfl_s += __shfl_down_sync(0xffffffffu, dfl_s, o);
        cnt   += __shfl_down_sync(0xffffffffu, cnt,   o);
    }

    __shared__ float sc[8], si[8], sd[8];
    __shared__ int   sp[8];
    int lane = threadIdx.x & 31;
    int warp = threadIdx.x >> 5;
    if (lane == 0) { sc[warp] = cls_s; si[warp] = iou_s; sd[warp] = dfl_s; sp[warp] = cnt; }
    __syncthreads();

    if (warp == 0) {
        cls_s = (lane < 8) ? sc[lane] : 0.f;
        iou_s = (lane < 8) ? si[lane] : 0.f;
        dfl_s = (lane < 8) ? sd[lane] : 0.f;
        cnt   = (lane < 8) ? sp[lane] : 0;
        #pragma unroll
        for (int o = 4; o > 0; o >>= 1) {
            cls_s += __shfl_down_sync(0xffffffffu, cls_s, o);
            iou_s += __shfl_down_sync(0xffffffffu, iou_s, o);
            dfl_s += __shfl_down_sync(0xffffffffu, dfl_s, o);
            cnt   += __shfl_down_sync(0xffffffffu, cnt,   o);
        }
        if (lane == 0) {
            atomicAdd(&g_acc[0], (double)cls_s);
            atomicAdd(&g_acc[1], (double)iou_s);
            atomicAdd(&g_acc[2], (double)dfl_s);
            atomicAdd(&g_acc[3], (double)cnt);
        }
    }
}

__global__ void finalize_kernel(float* __restrict__ out, int n) {
    double np = g_acc[3] < 1.0 ? 1.0 : g_acc[3];
    double total = g_acc[0] / np            // W_CLS = 1.0
                 + 7.5 * g_acc[1] / np      // W_IOU
                 + 1.5 * g_acc[2] / (np * 4.0); // W_DFL
    for (int i = 0; i < n; ++i) out[i] = (float)total;
}

extern "C" void kernel_launch(void* const* d_in, const int* in_sizes, int n_in,
                              void* d_out, int out_size) {
    const float* p0   = (const float*)d_in[0];
    const float* p1   = (const float*)d_in[1];
    const float* p2   = (const float*)d_in[2];
    const float* gtb  = (const float*)d_in[3];
    const int*   gtl  = (const int*)d_in[4];
    const int*   mind = (const int*)d_in[5];
    float* out = (float*)d_out;

    zero_acc_kernel<<<1, 1>>>();

    const int total = BATCH * NANCH;
    const int threads = 256;
    const int blocks = (total + threads - 1) / threads;
    yolo_loss_kernel<<<blocks, threads>>>(p0, p1, p2, gtb, gtl, mind);

    finalize_kernel<<<1, 1>>>(out, out_size);
}